// round 3
// baseline (speedup 1.0000x reference)
#include <cuda_runtime.h>
#include <cstdint>

#define BB 32
#define NN 128
#define DD 64
#define HH 8

// intermediates (device globals — no allocation allowed)
__device__ float g_Q[BB*NN*DD];
__device__ float g_K[BB*NN*DD];
__device__ float g_V[BB*NN*DD];
__device__ float g_attn[BB*NN*DD];

__device__ __forceinline__ void fma2(unsigned long long &d, unsigned long long a, unsigned long long b){
    asm("fma.rn.f32x2 %0, %1, %2, %0;" : "+l"(d) : "l"(a), "l"(b));
}
__device__ __forceinline__ unsigned long long pack2(float lo, float hi){
    unsigned long long r;
    asm("mov.b64 %0, {%1, %2};" : "=l"(r) : "f"(lo), "f"(hi));
    return r;
}
__device__ __forceinline__ void unpack2(float &lo, float &hi, unsigned long long v){
    asm("mov.b64 {%0, %1}, %2;" : "=f"(lo), "=f"(hi) : "l"(v));
}

// ---------------------------------------------------------------------------
// Kernel 1: Q/K/V projections. 16 rows per 256-thread block.
// Each thread owns column c for 4 rows -> each weight load feeds 12 FMAs.
// ---------------------------------------------------------------------------
__global__ __launch_bounds__(256) void qkv_kernel(
    const float* __restrict__ h,
    const float* __restrict__ Wq, const float* __restrict__ Wk, const float* __restrict__ Wv)
{
    __shared__ float sh[16][65];
    const int t = threadIdx.x, r = t >> 6, c = t & 63;
    const int row0 = blockIdx.x * 16;
#pragma unroll
    for (int rr = 0; rr < 4; ++rr)
        sh[rr*4 + r][c] = h[(row0 + rr*4 + r)*64 + c];
    __syncthreads();

    float q[4] = {0,0,0,0}, k[4] = {0,0,0,0}, v[4] = {0,0,0,0};
#pragma unroll 16
    for (int d = 0; d < 64; ++d){
        const float wq = Wq[d*64 + c];
        const float wk = Wk[d*64 + c];
        const float wv = Wv[d*64 + c];
#pragma unroll
        for (int rr = 0; rr < 4; ++rr){
            const float x = sh[rr*4 + r][d];
            q[rr] += x * wq;
            k[rr] += x * wk;
            v[rr] += x * wv;
        }
    }
#pragma unroll
    for (int rr = 0; rr < 4; ++rr){
        const int row = row0 + rr*4 + r;
        g_Q[row*64 + c] = q[rr];
        g_K[row*64 + c] = k[rr] * 0.35355339059327373f;   // DH^-0.5
        g_V[row*64 + c] = v[rr];
    }
}

// ---------------------------------------------------------------------------
// Kernel 2: main attention. One block per (i, b).
//   P = e[b,i,:,:] @ (We * Q_i)  [128 x 64] via packed f32x2 FMA
//   score[h,j] = sum_k P[j,h8+k] * K[b,j,h8+k]; clip/exp; * k_RW
//   attn = (s @ V) / max(sum s, 1e-6)
// Full e-tile transposed into smem once (no mid-GEMM sync). Accumulators are
// unpacked INLINE in the score phase (no P array -> no register spills).
// ---------------------------------------------------------------------------
__global__ __launch_bounds__(128, 4) void attn_kernel(
    const float* __restrict__ e,
    const float* __restrict__ We,
    const float* __restrict__ kRW)
{
    __shared__ __align__(16) float eT[64*132];   // e-tile transposed+rotated, 33.8KB
    __shared__ __align__(16) float Wp[64*64];    // We * Q_i
    __shared__ float sQ[64];
    __shared__ float sRW[128];
    __shared__ float red[16][8][10];

    const int t  = threadIdx.x;
    const int i  = blockIdx.x, b = blockIdx.y;
    const int jg = t & 15, hg = t >> 4;
    const int bi = b*NN + i;

    if (t < 64) sQ[t] = g_Q[bi*64 + t];
    sRW[t] = kRW[bi*128 + t];
    __syncthreads();

    // Wp[d][hk] = We[d][hk] * Q_i[hk]
#pragma unroll
    for (int rep = 0; rep < 32; ++rep){
        const int idx = rep*128 + t;
        Wp[idx] = We[idx] * sQ[idx & 63];
    }

    // Transpose full e tile: value e[j][d] at eT[d*132 + ((j + 4*((d>>2)&7)) & 127)]
    const float* eg = e + (size_t)bi * (NN*DD);
#pragma unroll
    for (int it = 0; it < 16; ++it){
        const int half = it >> 3;
        const int f    = (it & 7)*128 + t;
        const int j    = f >> 3;       // 0..127
        const int d4   = f & 7;        // quad within half
        const float4 v = *reinterpret_cast<const float4*>(eg + j*64 + half*32 + d4*4);
        const int pj   = (j + 4*d4) & 127;
        const int base = (half*32 + 4*d4)*132;
        eT[base +       pj] = v.x;
        eT[base + 132 + pj] = v.y;
        eT[base + 264 + pj] = v.z;
        eT[base + 396 + pj] = v.w;
    }
    __syncthreads();

    unsigned long long acc[2][2][8];
#pragma unroll
    for (int g = 0; g < 2; ++g)
#pragma unroll
        for (int p = 0; p < 2; ++p)
#pragma unroll
            for (int kk = 0; kk < 8; ++kk) acc[g][p][kk] = 0ull;

    const float* wrow = Wp + hg*8;
#pragma unroll 4
    for (int dl = 0; dl < 64; ++dl){
        const int rot = (dl >> 2) & 7;
        const int s0 = (jg + rot) & 31;
        const int s1 = (jg + 16 + rot) & 31;
        const ulonglong2 e0 = *reinterpret_cast<const ulonglong2*>(&eT[dl*132 + 4*s0]);
        const ulonglong2 e1 = *reinterpret_cast<const ulonglong2*>(&eT[dl*132 + 4*s1]);
        const float4 w0 = *reinterpret_cast<const float4*>(wrow + dl*64);
        const float4 w1 = *reinterpret_cast<const float4*>(wrow + dl*64 + 4);
        unsigned long long wd[8];
        wd[0] = pack2(w0.x, w0.x); wd[1] = pack2(w0.y, w0.y);
        wd[2] = pack2(w0.z, w0.z); wd[3] = pack2(w0.w, w0.w);
        wd[4] = pack2(w1.x, w1.x); wd[5] = pack2(w1.y, w1.y);
        wd[6] = pack2(w1.z, w1.z); wd[7] = pack2(w1.w, w1.w);
#pragma unroll
        for (int kk = 0; kk < 8; ++kk){
            fma2(acc[0][0][kk], e0.x, wd[kk]);
            fma2(acc[0][1][kk], e0.y, wd[kk]);
            fma2(acc[1][0][kk], e1.x, wd[kk]);
            fma2(acc[1][1][kk], e1.y, wd[kk]);
        }
    }

    // score + attn phase: unpack accumulators inline (keeps registers low)
    float denom = 0.f;
    float vacc[8] = {0.f,0.f,0.f,0.f,0.f,0.f,0.f,0.f};
    const float* Kb = g_K + (size_t)b*NN*64 + hg*8;
    const float* Vb = g_V + (size_t)b*NN*64 + hg*8;
#pragma unroll
    for (int g = 0; g < 2; ++g){
#pragma unroll
        for (int p = 0; p < 2; ++p){
            float pl[8], ph[8];
#pragma unroll
            for (int kk = 0; kk < 8; ++kk) unpack2(pl[kk], ph[kk], acc[g][p][kk]);
            const int jbase = (g << 6) + 4*jg + 2*p;
#pragma unroll
            for (int half = 0; half < 2; ++half){
                const float* P = half ? ph : pl;
                const int j = jbase + half;
                const float4 k0 = *reinterpret_cast<const float4*>(Kb + j*64);
                const float4 k1 = *reinterpret_cast<const float4*>(Kb + j*64 + 4);
                float sc = P[0]*k0.x + P[1]*k0.y + P[2]*k0.z + P[3]*k0.w
                         + P[4]*k1.x + P[5]*k1.y + P[6]*k1.z + P[7]*k1.w;
                sc = fminf(fmaxf(sc, -5.f), 5.f);
                const float s = __expf(sc) * sRW[j];
                denom += s;
                const float4 v0 = *reinterpret_cast<const float4*>(Vb + j*64);
                const float4 v1 = *reinterpret_cast<const float4*>(Vb + j*64 + 4);
                vacc[0] += s*v0.x; vacc[1] += s*v0.y; vacc[2] += s*v0.z; vacc[3] += s*v0.w;
                vacc[4] += s*v1.x; vacc[5] += s*v1.y; vacc[6] += s*v1.z; vacc[7] += s*v1.w;
            }
        }
    }

#pragma unroll
    for (int kk = 0; kk < 8; ++kk) red[jg][hg][kk] = vacc[kk];
    red[jg][hg][8] = denom;
    __syncthreads();
    if (t < 64){
        const int hh = t >> 3, dd = t & 7;
        float s = 0.f, den = 0.f;
#pragma unroll
        for (int q = 0; q < 16; ++q){ s += red[q][hh][dd]; den += red[q][hh][8]; }
        den = fmaxf(den, 1e-6f);
        g_attn[bi*64 + hh*8 + dd] = s / den;
    }
}

// ---------------------------------------------------------------------------
// Kernel 3: O-proj + residual + LN1 + FFN + LN2. 16 rows per 256-thread block.
// ---------------------------------------------------------------------------
__global__ __launch_bounds__(256) void tail_kernel(
    const float* __restrict__ h,
    const float* __restrict__ Wo, const float* __restrict__ bo,
    const float* __restrict__ g1, const float* __restrict__ b1g,
    const float* __restrict__ W1, const float* __restrict__ b1,
    const float* __restrict__ W2, const float* __restrict__ b2,
    const float* __restrict__ g2, const float* __restrict__ b2g,
    float* __restrict__ out)
{
    __shared__ float sa[16][65];
    __shared__ float sx[16][65];
    __shared__ float shd[16][130];
    const int t = threadIdx.x, r = t >> 6, c = t & 63;
    const int row0 = blockIdx.x * 16;

#pragma unroll
    for (int rr = 0; rr < 4; ++rr)
        sa[rr*4 + r][c] = g_attn[(row0 + rr*4 + r)*64 + c];
    __syncthreads();

    // O projection + residual
    float x[4];
#pragma unroll
    for (int rr = 0; rr < 4; ++rr)
        x[rr] = bo[c] + h[(row0 + rr*4 + r)*64 + c];
#pragma unroll 16
    for (int d = 0; d < 64; ++d){
        const float w = Wo[d*64 + c];
#pragma unroll
        for (int rr = 0; rr < 4; ++rr) x[rr] += sa[rr*4 + r][d] * w;
    }

    // LN1
#pragma unroll
    for (int rr = 0; rr < 4; ++rr) sx[rr*4 + r][c] = x[rr];
    __syncthreads();
    float h1[4];
#pragma unroll
    for (int rr = 0; rr < 4; ++rr){
        const int lr = rr*4 + r;
        float m = 0.f;
#pragma unroll 16
        for (int d = 0; d < 64; ++d) m += sx[lr][d];
        m *= (1.f/64.f);
        float v = 0.f;
#pragma unroll 16
        for (int d = 0; d < 64; ++d){ const float df = sx[lr][d] - m; v += df*df; }
        v *= (1.f/64.f);
        h1[rr] = (x[rr] - m) * rsqrtf(v + 1e-5f) * g1[c] + b1g[c];
    }
    __syncthreads();
#pragma unroll
    for (int rr = 0; rr < 4; ++rr) sx[rr*4 + r][c] = h1[rr];
    __syncthreads();

    // FFN up (128 hidden; thread c owns units c and c+64)
    float a0[4], a1[4];
#pragma unroll
    for (int rr = 0; rr < 4; ++rr){ a0[rr] = b1[c]; a1[rr] = b1[c + 64]; }
#pragma unroll 16
    for (int d = 0; d < 64; ++d){
        const float wa = W1[d*128 + c];
        const float wb = W1[d*128 + c + 64];
#pragma unroll
        for (int rr = 0; rr < 4; ++rr){
            const float xv = sx[rr*4 + r][d];
            a0[rr] += xv * wa;
            a1[rr] += xv * wb;
        }
    }
#pragma unroll
    for (int rr = 0; rr < 4; ++rr){
        shd[rr*4 + r][c]      = fmaxf(a0[rr], 0.f);
        shd[rr*4 + r][c + 64] = fmaxf(a1[rr], 0.f);
    }
    __syncthreads();
    float ff[4];
#pragma unroll
    for (int rr = 0; rr < 4; ++rr) ff[rr] = b2[c];
#pragma unroll 16
    for (int u = 0; u < 128; ++u){
        const float w = W2[u*64 + c];
#pragma unroll
        for (int rr = 0; rr < 4; ++rr) ff[rr] += shd[rr*4 + r][u] * w;
    }

    // LN2
    __syncthreads();
#pragma unroll
    for (int rr = 0; rr < 4; ++rr) sa[rr*4 + r][c] = h1[rr] + ff[rr];
    __syncthreads();
#pragma unroll
    for (int rr = 0; rr < 4; ++rr){
        const int lr = rr*4 + r;
        const float x2 = sa[lr][c];
        float m2 = 0.f;
#pragma unroll 16
        for (int d = 0; d < 64; ++d) m2 += sa[lr][d];
        m2 *= (1.f/64.f);
        float v2 = 0.f;
#pragma unroll 16
        for (int d = 0; d < 64; ++d){ const float df = sa[lr][d] - m2; v2 += df*df; }
        v2 *= (1.f/64.f);
        out[(row0 + lr)*64 + c] = (x2 - m2) * rsqrtf(v2 + 1e-5f) * g2[c] + b2g[c];
    }
}

// ---------------------------------------------------------------------------
extern "C" void kernel_launch(void* const* d_in, const int* in_sizes, int n_in,
                              void* d_out, int out_size)
{
    (void)in_sizes; (void)n_in; (void)out_size;
    const float* h   = (const float*)d_in[0];
    // d_in[1] = p, unused by the reference
    const float* e   = (const float*)d_in[2];
    const float* kRW = (const float*)d_in[3];
    const float* Wq  = (const float*)d_in[4];
    const float* Wk  = (const float*)d_in[5];
    const float* We  = (const float*)d_in[6];
    const float* Wv  = (const float*)d_in[7];
    const float* Wo  = (const float*)d_in[8];
    const float* bo  = (const float*)d_in[9];
    const float* g1  = (const float*)d_in[10];
    const float* b1g = (const float*)d_in[11];
    const float* W1  = (const float*)d_in[12];
    const float* b1  = (const float*)d_in[13];
    const float* W2  = (const float*)d_in[14];
    const float* b2  = (const float*)d_in[15];
    const float* g2  = (const float*)d_in[16];
    const float* b2g = (const float*)d_in[17];
    float* out = (float*)d_out;

    qkv_kernel<<<BB*NN/16, 256>>>(h, Wq, Wk, Wv);
    dim3 grid(NN, BB);
    attn_kernel<<<grid, 128>>>(e, We, kRW);
    tail_kernel<<<BB*NN/16, 256>>>(h, Wo, bo, g1, b1g, W1, b1, W2, b2, g2, b2g, out);
}

// round 4
// speedup vs baseline: 1.3703x; 1.3703x over previous
#include <cuda_runtime.h>
#include <cstdint>

#define BB 32
#define NN 128
#define DD 64
#define HH 8

// intermediates (device globals — no allocation allowed)
__device__ float g_Q[BB*NN*DD];
__device__ float g_K[BB*NN*DD];
__device__ float g_V[BB*NN*DD];
__device__ float g_attn[BB*NN*DD];

__device__ __forceinline__ void fma2(unsigned long long &d, unsigned long long a, unsigned long long b){
    asm("fma.rn.f32x2 %0, %1, %2, %0;" : "+l"(d) : "l"(a), "l"(b));
}
__device__ __forceinline__ unsigned long long pack2(float lo, float hi){
    unsigned long long r;
    asm("mov.b64 %0, {%1, %2};" : "=l"(r) : "f"(lo), "f"(hi));
    return r;
}
__device__ __forceinline__ void unpack2(float &lo, float &hi, unsigned long long v){
    asm("mov.b64 {%0, %1}, %2;" : "=f"(lo), "=f"(hi) : "l"(v));
}

// ---------------------------------------------------------------------------
// Kernel 1: Q/K/V projections. 8 rows per 256-thread block, grid 512.
// Weights staged once per block into smem; each thread computes 2 rows.
// ---------------------------------------------------------------------------
__global__ __launch_bounds__(256) void qkv_kernel(
    const float* __restrict__ h,
    const float* __restrict__ Wq, const float* __restrict__ Wk, const float* __restrict__ Wv)
{
    extern __shared__ float sm_q[];
    float* sW = sm_q;            // 3 * 4096 floats
    float* sh = sm_q + 12288;    // 512 floats
    const int t = threadIdx.x, c = t & 63, r = t >> 6;
    const int row0 = blockIdx.x * 8;
#pragma unroll
    for (int rep = 0; rep < 16; ++rep) sW[rep*256 + t]        = Wq[rep*256 + t];
#pragma unroll
    for (int rep = 0; rep < 16; ++rep) sW[4096 + rep*256 + t] = Wk[rep*256 + t];
#pragma unroll
    for (int rep = 0; rep < 16; ++rep) sW[8192 + rep*256 + t] = Wv[rep*256 + t];
    sh[t]       = h[row0*64 + t];
    sh[256 + t] = h[row0*64 + 256 + t];
    __syncthreads();

    const int rA = r, rB = r + 4;
    float q0=0,k0=0,v0=0,q1=0,k1=0,v1=0;
#pragma unroll 16
    for (int d = 0; d < 64; ++d){
        const float wq = sW[d*64 + c];
        const float wk = sW[4096 + d*64 + c];
        const float wv = sW[8192 + d*64 + c];
        const float xa = sh[rA*64 + d];
        const float xb = sh[rB*64 + d];
        q0 += xa*wq; k0 += xa*wk; v0 += xa*wv;
        q1 += xb*wq; k1 += xb*wk; v1 += xb*wv;
    }
    const float kscale = 0.35355339059327373f; // DH^-0.5
    g_Q[(row0+rA)*64 + c] = q0;
    g_K[(row0+rA)*64 + c] = k0 * kscale;
    g_V[(row0+rA)*64 + c] = v0;
    g_Q[(row0+rB)*64 + c] = q1;
    g_K[(row0+rB)*64 + c] = k1 * kscale;
    g_V[(row0+rB)*64 + c] = v1;
}

// ---------------------------------------------------------------------------
// Kernel 2: main attention. One block per (i, b), 128 threads = 4 warps.
// Warp w owns hk in [16w, 16w+16); thread lane jg owns j-quad {4jg..4jg+3}.
//  Phase A: P = e_tile @ (We*Q_i) via packed f32x2 FMA (Wp reads warp-uniform).
//  Phase B: stage K transposed; scores -> smem sS[8][132].
//  Phase C: attn = (sS @ V)/denom with coalesced V LDGs (remapped threads).
// Dynamic smem: buf 8448 | Wp 4096 | sS 1056 | sQ 64 | sRW 128 = 13792 floats.
// ---------------------------------------------------------------------------
__global__ __launch_bounds__(128, 4) void attn_kernel(
    const float* __restrict__ e,
    const float* __restrict__ We,
    const float* __restrict__ kRW)
{
    extern __shared__ float sm[];
    float* buf = sm;            // 8448 floats: eT -> sK -> reduction
    float* Wp  = sm + 8448;     // 4096
    float* sS  = sm + 12544;    // 8*132
    float* sQ  = sm + 13600;    // 64
    float* sRW = sm + 13664;    // 128

    const int t   = threadIdx.x;
    const int i   = blockIdx.x, b = blockIdx.y;
    const int jg  = t & 31;     // j-quad index 0..31
    const int hgg = t >> 5;     // warp id = hk group (16 hk each)
    const int bi  = b*NN + i;

    if (t < 64) sQ[t] = g_Q[bi*64 + t];
    sRW[t] = kRW[bi*128 + t];
    __syncthreads();

    // Wp[d][hk] = We[d][hk] * Q_i[hk]
#pragma unroll
    for (int rep = 0; rep < 32; ++rep){
        const int idx = rep*128 + t;
        Wp[idx] = We[idx] * sQ[idx & 63];
    }

    // Transpose e tile: e[j][d] -> buf[d*132 + ((j + 4*((d>>2)&7)) & 127)]
    const float* eg = e + (size_t)bi * (NN*DD);
#pragma unroll
    for (int it = 0; it < 16; ++it){
        const int half = it >> 3;
        const int f    = (it & 7)*128 + t;
        const int j    = f >> 3;
        const int d4   = f & 7;
        const float4 v = *reinterpret_cast<const float4*>(eg + j*64 + half*32 + d4*4);
        const int pj   = (j + 4*d4) & 127;
        const int base = (half*32 + 4*d4)*132;
        buf[base +       pj] = v.x;
        buf[base + 132 + pj] = v.y;
        buf[base + 264 + pj] = v.z;
        buf[base + 396 + pj] = v.w;
    }
    __syncthreads();

    // Phase A: GEMM. acc0/acc1 hold packed (j0,j1)/(j2,j3) for 16 hk.
    unsigned long long acc0[16], acc1[16];
#pragma unroll
    for (int kk = 0; kk < 16; ++kk){ acc0[kk] = 0ull; acc1[kk] = 0ull; }

#pragma unroll 4
    for (int dl = 0; dl < 64; ++dl){
        const int rot = (dl >> 2) & 7;
        const ulonglong2 e2 = *reinterpret_cast<const ulonglong2*>(
            &buf[dl*132 + 4*((jg + rot) & 31)]);
        const float4* wr = reinterpret_cast<const float4*>(&Wp[dl*64 + hgg*16]);
#pragma unroll
        for (int wq = 0; wq < 4; ++wq){
            const float4 w = wr[wq];   // warp-uniform -> broadcast
            const unsigned long long wd0 = pack2(w.x, w.x);
            const unsigned long long wd1 = pack2(w.y, w.y);
            const unsigned long long wd2 = pack2(w.z, w.z);
            const unsigned long long wd3 = pack2(w.w, w.w);
            fma2(acc0[4*wq+0], e2.x, wd0); fma2(acc1[4*wq+0], e2.y, wd0);
            fma2(acc0[4*wq+1], e2.x, wd1); fma2(acc1[4*wq+1], e2.y, wd1);
            fma2(acc0[4*wq+2], e2.x, wd2); fma2(acc1[4*wq+2], e2.y, wd2);
            fma2(acc0[4*wq+3], e2.x, wd3); fma2(acc1[4*wq+3], e2.y, wd3);
        }
    }
    __syncthreads();   // everyone done reading eT

    // Phase B: stage K transposed into buf (same rotation layout)
    const float* Kg = g_K + (size_t)b*NN*64;
#pragma unroll
    for (int it = 0; it < 16; ++it){
        const int half = it >> 3;
        const int f    = (it & 7)*128 + t;
        const int j    = f >> 3;
        const int d4   = f & 7;
        const float4 v = *reinterpret_cast<const float4*>(Kg + j*64 + half*32 + d4*4);
        const int pj   = (j + 4*d4) & 127;
        const int base = (half*32 + 4*d4)*132;
        buf[base +       pj] = v.x;
        buf[base + 132 + pj] = v.y;
        buf[base + 264 + pj] = v.z;
        buf[base + 396 + pj] = v.w;
    }
    __syncthreads();

    // scores for this thread's 4 j over its 2 heads
    float sc[4][2] = {{0,0},{0,0},{0,0},{0,0}};
#pragma unroll
    for (int kk = 0; kk < 16; ++kk){
        const int hk   = hgg*16 + kk;
        const int rotk = (hk >> 2) & 7;
        const float4 k4 = *reinterpret_cast<const float4*>(
            &buf[hk*132 + 4*((jg + rotk) & 31)]);
        float p0,p1,p2,p3;
        unpack2(p0, p1, acc0[kk]);
        unpack2(p2, p3, acc1[kk]);
        const int hh = kk >> 3;
        sc[0][hh] += p0*k4.x;
        sc[1][hh] += p1*k4.y;
        sc[2][hh] += p2*k4.z;
        sc[3][hh] += p3*k4.w;
    }
#pragma unroll
    for (int hh = 0; hh < 2; ++hh){
        float4 y;
        float* yp = &y.x;
#pragma unroll
        for (int jj = 0; jj < 4; ++jj){
            float s = fminf(fmaxf(sc[jj][hh], -5.f), 5.f);
            yp[jj] = __expf(s) * sRW[4*jg + jj];
        }
        *reinterpret_cast<float4*>(&sS[(hgg*2 + hh)*132 + 4*jg]) = y;
    }
    __syncthreads();

    // Phase C: attn = (sS @ V) / denom, coalesced V loads.
    {
        const int o = t & 63, u = t >> 6;
        const int hR = o >> 3;
        const float* Vg = g_V + (size_t)b*NN*64 + (size_t)u*64*64 + o;
        const float* Sr = sS + hR*132 + u*64;
        float vsum = 0.f, dsum = 0.f;
#pragma unroll 8
        for (int jj = 0; jj < 64; ++jj){
            const float s = Sr[jj];
            const float v = Vg[jj*64];
            vsum += s*v;
            dsum += s;
        }
        buf[t]       = vsum;   // buf free now (sK fully consumed pre-sync)
        buf[128 + t] = dsum;
    }
    __syncthreads();
    if (t < 64){
        const float v = buf[t] + buf[64 + t];
        const float d = buf[128 + t] + buf[192 + t];
        g_attn[bi*64 + t] = v / fmaxf(d, 1e-6f);
    }
}

// ---------------------------------------------------------------------------
// Kernel 3: O-projection + residual + LN1 + FFN + LN2.  4 rows / 256 threads.
// (round-2 proven version)
// ---------------------------------------------------------------------------
__global__ __launch_bounds__(256) void tail_kernel(
    const float* __restrict__ h,
    const float* __restrict__ Wo, const float* __restrict__ bo,
    const float* __restrict__ g1, const float* __restrict__ b1g,
    const float* __restrict__ W1, const float* __restrict__ b1,
    const float* __restrict__ W2, const float* __restrict__ b2,
    const float* __restrict__ g2, const float* __restrict__ b2g,
    float* __restrict__ out)
{
    __shared__ float sa[4][65];
    __shared__ float sx[4][65];
    __shared__ float shd[4][130];
    const int t = threadIdx.x, r = t >> 6, c = t & 63;
    const int row = blockIdx.x * 4 + r;

    sa[r][c] = g_attn[row*64 + c];
    __syncthreads();
    float x = bo[c] + h[row*64 + c];
#pragma unroll 8
    for (int d = 0; d < 64; ++d) x += sa[r][d] * Wo[d*64 + c];

    // LN1
    sx[r][c] = x;
    __syncthreads();
    float m = 0.f;
#pragma unroll 8
    for (int d = 0; d < 64; ++d) m += sx[r][d];
    m *= (1.f/64.f);
    float v = 0.f;
#pragma unroll 8
    for (int d = 0; d < 64; ++d){ const float df = sx[r][d] - m; v += df*df; }
    v *= (1.f/64.f);
    const float h1 = (x - m) * rsqrtf(v + 1e-5f) * g1[c] + b1g[c];
    __syncthreads();
    sx[r][c] = h1;
    __syncthreads();

    // FFN up (2D = 128 hidden units; thread c owns units c and c+64)
    float a0 = b1[c], a1 = b1[c + 64];
#pragma unroll 8
    for (int d = 0; d < 64; ++d){
        const float xv = sx[r][d];
        a0 += xv * W1[d*128 + c];
        a1 += xv * W1[d*128 + c + 64];
    }
    shd[r][c]      = fmaxf(a0, 0.f);
    shd[r][c + 64] = fmaxf(a1, 0.f);
    __syncthreads();
    float ff = b2[c];
#pragma unroll 8
    for (int u = 0; u < 128; ++u) ff += shd[r][u] * W2[u*64 + c];
    const float x2 = h1 + ff;

    // LN2
    __syncthreads();
    sa[r][c] = x2;
    __syncthreads();
    float m2 = 0.f;
#pragma unroll 8
    for (int d = 0; d < 64; ++d) m2 += sa[r][d];
    m2 *= (1.f/64.f);
    float v2 = 0.f;
#pragma unroll 8
    for (int d = 0; d < 64; ++d){ const float df = sa[r][d] - m2; v2 += df*df; }
    v2 *= (1.f/64.f);
    out[row*64 + c] = (x2 - m2) * rsqrtf(v2 + 1e-5f) * g2[c] + b2g[c];
}

// ---------------------------------------------------------------------------
extern "C" void kernel_launch(void* const* d_in, const int* in_sizes, int n_in,
                              void* d_out, int out_size)
{
    (void)in_sizes; (void)n_in; (void)out_size;
    const float* h   = (const float*)d_in[0];
    // d_in[1] = p, unused by the reference
    const float* e   = (const float*)d_in[2];
    const float* kRW = (const float*)d_in[3];
    const float* Wq  = (const float*)d_in[4];
    const float* Wk  = (const float*)d_in[5];
    const float* We  = (const float*)d_in[6];
    const float* Wv  = (const float*)d_in[7];
    const float* Wo  = (const float*)d_in[8];
    const float* bo  = (const float*)d_in[9];
    const float* g1  = (const float*)d_in[10];
    const float* b1g = (const float*)d_in[11];
    const float* W1  = (const float*)d_in[12];
    const float* b1  = (const float*)d_in[13];
    const float* W2  = (const float*)d_in[14];
    const float* b2  = (const float*)d_in[15];
    const float* g2  = (const float*)d_in[16];
    const float* b2g = (const float*)d_in[17];
    float* out = (float*)d_out;

    const int qkv_smem  = 12800 * 4;   // 51200 B
    const int attn_smem = 13792 * 4;   // 55168 B
    cudaFuncSetAttribute((const void*)qkv_kernel,
                         cudaFuncAttributeMaxDynamicSharedMemorySize, qkv_smem);
    cudaFuncSetAttribute((const void*)attn_kernel,
                         cudaFuncAttributeMaxDynamicSharedMemorySize, attn_smem);

    qkv_kernel<<<BB*NN/8, 256, qkv_smem>>>(h, Wq, Wk, Wv);
    dim3 grid(NN, BB);
    attn_kernel<<<grid, 128, attn_smem>>>(e, We, kRW);
    tail_kernel<<<BB*NN/4, 256>>>(h, Wo, bo, g1, b1g, W1, b1, W2, b2, g2, b2g, out);
}